// round 16
// baseline (speedup 1.0000x reference)
#include <cuda_runtime.h>
#include <cuda_fp16.h>
#include <cstdint>
#include <math.h>

// Problem constants
#define BB 4
#define SS 1024
#define CC 1280
#define HH 20
#define DD 64
#define SC2 0.18033688011112042f      // 64^-0.5 * log2(e)
#define EPSV 1e-5f

// ---------------- scratch (static device allocations are allowed) -----------
#define XN (BB*SS*CC)     // 5242880
#define WN (CC*CC)        // 1638400
__device__ __align__(16) __half g_xh[XN + 4*WN];   // fp16 [X | Wq | Wk | Wv | Wo]
__device__ __align__(16) __half g_qp[BB*SS*CC];    // fp16 Q (pre-AdaIN)
__device__ __align__(16) __half g_kp[BB*SS*CC];    // fp16 K (pre-AdaIN)
__device__ __align__(16) __half g_kh[BB*SS*CC];    // fp16 AdaIN'd K
__device__ __align__(16) __half g_vh[BB*SS*CC];    // fp16 V (from GEMM)
__device__ __align__(16) __half g_attnh[BB*SS*CC]; // fp16 attention output
__device__ float  g_psum[2*BB*8*CC];               // stats partials [z][b][seg][c]
__device__ float  g_psq [2*BB*8*CC];
__device__ float  g_scl[2*BB*CC];
__device__ float  g_shf[2*BB*CC];
__device__ int    g_ctr;                           // attention work-queue counter

// =================== helpers (sm_75+/sm_80+ PTX, base-target safe) =========
__device__ __forceinline__ float fexp2(float x) {
    float y;
    asm("ex2.approx.f32 %0, %1;" : "=f"(y) : "f"(x));
    return y;
}

__device__ __forceinline__ void mma_16816(
    float c[4], const uint32_t a[4], uint32_t b0, uint32_t b1)
{
    asm volatile(
        "mma.sync.aligned.m16n8k16.row.col.f32.f16.f16.f32 "
        "{%0,%1,%2,%3}, {%4,%5,%6,%7}, {%8,%9}, {%0,%1,%2,%3};\n"
        : "+f"(c[0]), "+f"(c[1]), "+f"(c[2]), "+f"(c[3])
        : "r"(a[0]), "r"(a[1]), "r"(a[2]), "r"(a[3]), "r"(b0), "r"(b1));
}

__device__ __forceinline__ uint32_t smem_u32(const void* p) {
    uint32_t a;
    asm("{ .reg .u64 t; cvta.to.shared.u64 t, %1; cvt.u32.u64 %0, t; }"
        : "=r"(a) : "l"(p));
    return a;
}

__device__ __forceinline__ uint32_t pack_h2(float a, float b) {
    __half2 t = __floats2half2_rn(a, b);
    return *(uint32_t*)&t;
}

#define LDSM_X4(R, addr) \
    asm volatile("ldmatrix.sync.aligned.m8n8.x4.shared.b16 {%0,%1,%2,%3}, [%4];" \
        : "=r"((R)[0]), "=r"((R)[1]), "=r"((R)[2]), "=r"((R)[3]) : "r"(addr))

#define LDSM_X4T(R, addr) \
    asm volatile("ldmatrix.sync.aligned.m8n8.x4.trans.shared.b16 {%0,%1,%2,%3}, [%4];" \
        : "=r"((R)[0]), "=r"((R)[1]), "=r"((R)[2]), "=r"((R)[3]) : "r"(addr))

#define CP_ASYNC16(dst, src) \
    asm volatile("cp.async.cg.shared.global [%0], [%1], 16;" \
        :: "r"(dst), "l"(src))
#define CP_COMMIT() asm volatile("cp.async.commit_group;")
#define CP_WAIT1()  asm volatile("cp.async.wait_group 1;")

// ---------------------------------------------------------------------------
// fp16 conversion pass over [X | Wq | Wk | Wv | Wo] + work-queue reset
// ---------------------------------------------------------------------------
#define CVT_F4 ((XN + 4*WN) / 4)
__global__ __launch_bounds__(256) void k_cvt(
    const float* __restrict__ X,  const float* __restrict__ Wq,
    const float* __restrict__ Wk, const float* __restrict__ Wv,
    const float* __restrict__ Wo)
{
    if (blockIdx.x == 0 && threadIdx.x == 0) g_ctr = 0;
    int i4 = blockIdx.x * 256 + threadIdx.x;
    if (i4 >= CVT_F4) return;
    const float* src;
    int base;
    if      (i4 < XN/4)          { src = X;  base = 0; }
    else if (i4 < (XN+WN)/4)     { src = Wq; base = XN/4; }
    else if (i4 < (XN+2*WN)/4)   { src = Wk; base = (XN+WN)/4; }
    else if (i4 < (XN+3*WN)/4)   { src = Wv; base = (XN+2*WN)/4; }
    else                         { src = Wo; base = (XN+3*WN)/4; }
    float4 v = ((const float4*)src)[i4 - base];
    uint2 t;
    t.x = pack_h2(v.x, v.y);
    t.y = pack_h2(v.z, v.w);
    ((uint2*)g_xh)[i4] = t;
}

// ---------------------------------------------------------------------------
// Tensor-core fp16 GEMM (fp32 accum): C = A @ W^T (+bias). Inputs fp16.
// Block 128x128, BK=32 fp16, 3-stage cp.async, one barrier per k-tile.
// For sz>=0 (Q:0, K:1) the epilogue also emits per-column partial
// sum / sum-of-squares stats (no atomics: each (row-tile, col-tile) pair
// owns a unique (z,b,seg,c) slot).
// ---------------------------------------------------------------------------
#define GKT (CC / 32)   // 40 k-tiles
#define GST 10240
#define GBOFF 30720
#define GEMM_SMEM 61440

#define GISSUE(t, s) do { \
    uint32_t _da = base + (s) * GST + stoff; \
    uint32_t _db = base + GBOFF + (s) * GST + stoff; \
    const __half* _An = Ap + (t) * 32; \
    const __half* _Bn = Bp + (t) * 32; \
    CP_ASYNC16(_da,      _An); \
    CP_ASYNC16(_da + 16, _An + 8); \
    CP_ASYNC16(_db,      _Bn); \
    CP_ASYNC16(_db + 16, _Bn + 8); \
} while (0)

__device__ __forceinline__ void gemm_mma_body(
    const __half* __restrict__ A, const __half* __restrict__ W,
    const float* __restrict__ bias, float* __restrict__ CoutF,
    __half* __restrict__ CoutH, int sz)
{
    extern __shared__ __align__(16) uint32_t gsm[];

    const int tid  = threadIdx.x;
    const int warp = tid >> 5, lane = tid & 31;
    const int wm   = (warp & 3) * 32;
    const int wn   = (warp >> 2) * 64;
    const int tg   = lane & 3, gid = lane >> 2;
    const int m0   = blockIdx.y * 128;
    const int n0   = blockIdx.x * 128;

    const int lrow = tid >> 1;
    const int lc   = (tid & 1) * 16;
    const __half* Ap = A + (size_t)(m0 + lrow) * CC + lc;
    const __half* Bp = W + (size_t)(n0 + lrow) * CC + lc;

    const uint32_t base  = smem_u32(gsm);
    const uint32_t stoff = (uint32_t)(lrow * 40 + lc) * 2;

    const int lr = lane & 7;
    const uint32_t aoff = ((wm + ((lane >> 3) & 1) * 8 + lr) * 40
                           + ((lane >> 4) & 1) * 8) * 2;
    const uint32_t boff = ((wn + (lane >> 4) * 8 + lr) * 40
                           + ((lane >> 3) & 1) * 8) * 2;

    float acc[2][8][4];
#pragma unroll
    for (int im = 0; im < 2; im++)
#pragma unroll
        for (int in_ = 0; in_ < 8; in_++)
#pragma unroll
            for (int r = 0; r < 4; r++) acc[im][in_][r] = 0.f;

    GISSUE(0, 0); CP_COMMIT();
    GISSUE(1, 1); CP_COMMIT();

    int cs = 0;
    for (int kt = 0; kt < GKT; kt++) {
        CP_WAIT1();
        __syncthreads();

        int is_ = cs + 2; if (is_ >= 3) is_ -= 3;
        if (kt + 2 < GKT) GISSUE(kt + 2, is_);
        CP_COMMIT();

        const uint32_t sal = base + cs * GST + aoff;
        const uint32_t sbl = base + GBOFF + cs * GST + boff;
#pragma unroll
        for (int ks = 0; ks < 2; ks++) {
            uint32_t af[2][4];
            uint32_t bf[4][4];
            LDSM_X4(af[0], sal + ks * 32);
            LDSM_X4(af[1], sal + 16 * 80 + ks * 32);
#pragma unroll
            for (int np = 0; np < 4; np++)
                LDSM_X4(bf[np], sbl + np * 16 * 80 + ks * 32);
#pragma unroll
            for (int np = 0; np < 4; np++) {
                mma_16816(acc[0][2*np],     af[0], bf[np][0], bf[np][1]);
                mma_16816(acc[0][2*np + 1], af[0], bf[np][2], bf[np][3]);
                mma_16816(acc[1][2*np],     af[1], bf[np][0], bf[np][1]);
                mma_16816(acc[1][2*np + 1], af[1], bf[np][2], bf[np][3]);
            }
        }
        if (++cs == 3) cs = 0;
    }

    // ---- output store ----
#pragma unroll
    for (int im = 0; im < 2; im++) {
        int row = m0 + wm + im * 16 + gid;
#pragma unroll
        for (int in_ = 0; in_ < 8; in_++) {
            int col = n0 + wn + in_ * 8 + tg * 2;
            if (CoutH) {
                uint32_t lo = pack_h2(acc[im][in_][0], acc[im][in_][1]);
                uint32_t hi = pack_h2(acc[im][in_][2], acc[im][in_][3]);
                *(uint32_t*)(CoutH + (size_t)row * CC + col)       = lo;
                *(uint32_t*)(CoutH + (size_t)(row + 8) * CC + col) = hi;
            } else {
                float b0v = 0.f, b1v = 0.f;
                if (bias) { b0v = bias[col]; b1v = bias[col + 1]; }
                float2 lo = make_float2(acc[im][in_][0] + b0v, acc[im][in_][1] + b1v);
                float2 hi = make_float2(acc[im][in_][2] + b0v, acc[im][in_][3] + b1v);
                *(float2*)(CoutF + (size_t)row * CC + col)       = lo;
                *(float2*)(CoutF + (size_t)(row + 8) * CC + col) = hi;
            }
        }
    }

    // ---- fused stats partials (Q/K only) ----
    if (sz >= 0) {
        __syncthreads();                 // all smem reads done; reuse as scratch
        float* red = (float*)gsm;        // [2 metrics][4 m-warps][128 cols]
        float cstat[2][16];
#pragma unroll
        for (int in_ = 0; in_ < 8; in_++) {
#pragma unroll
            for (int t2 = 0; t2 < 2; t2++) {
                float a0 = acc[0][in_][t2],     a1 = acc[0][in_][2 + t2];
                float a2 = acc[1][in_][t2],     a3 = acc[1][in_][2 + t2];
                float s = (a0 + a1) + (a2 + a3);
                float q = fmaf(a0, a0, fmaf(a1, a1, fmaf(a2, a2, a3 * a3)));
                s += __shfl_xor_sync(0xffffffffu, s, 4);
                s += __shfl_xor_sync(0xffffffffu, s, 8);
                s += __shfl_xor_sync(0xffffffffu, s, 16);
                q += __shfl_xor_sync(0xffffffffu, q, 4);
                q += __shfl_xor_sync(0xffffffffu, q, 8);
                q += __shfl_xor_sync(0xffffffffu, q, 16);
                cstat[0][in_ * 2 + t2] = s;
                cstat[1][in_ * 2 + t2] = q;
            }
        }
        if (lane < 4) {   // gid == 0, tg == lane
#pragma unroll
            for (int in_ = 0; in_ < 8; in_++)
#pragma unroll
                for (int t2 = 0; t2 < 2; t2++) {
                    int cl = wn + in_ * 8 + tg * 2 + t2;
                    red[(warp & 3) * 128 + cl]       = cstat[0][in_ * 2 + t2];
                    red[512 + (warp & 3) * 128 + cl] = cstat[1][in_ * 2 + t2];
                }
        }
        __syncthreads();
        const int m  = tid >> 7;         // 0: sum, 1: sumsq
        const int cl = tid & 127;
        float v = red[m * 512 + cl] + red[m * 512 + 128 + cl]
                + red[m * 512 + 256 + cl] + red[m * 512 + 384 + cl];
        const int bb_ = (int)blockIdx.y >> 3, seg = (int)blockIdx.y & 7;
        const int idx = ((sz * BB + bb_) * 8 + seg) * CC + n0 + cl;
        if (m == 0) g_psum[idx] = v;
        else        g_psq [idx] = v;
    }
}

__global__ __launch_bounds__(256) void k_qkv_mma()
{
    const __half* X = g_xh;
    const __half* W = g_xh + XN + (size_t)blockIdx.z * WN;
    if (blockIdx.z == 0)      gemm_mma_body(X, W, nullptr, nullptr, g_qp, 0);
    else if (blockIdx.z == 1) gemm_mma_body(X, W, nullptr, nullptr, g_kp, 1);
    else                      gemm_mma_body(X, W, nullptr, nullptr, g_vh, -1);
}

__global__ __launch_bounds__(256) void k_proj_mma(
    const float* __restrict__ bo, float* __restrict__ out)
{
    gemm_mma_body(g_attnh, g_xh + XN + 3 * (size_t)WN, bo, out, nullptr, -1);
}

// ---------------------------------------------------------------------------
// finalize: reduce 8 segments, build AdaIN affine (scl, shf)
// ---------------------------------------------------------------------------
__global__ void k_finalize()
{
    int i = blockIdx.x * 256 + threadIdx.x;
    if (i >= 2 * BB * CC) return;
    int c  = i % CC;
    int b  = (i / CC) % BB;
    int z  = i / (CC * BB);
    int sb = (b < BB / 2) ? 0 : BB / 2;

    float sum = 0, sq = 0, sums = 0, sqs = 0;
#pragma unroll
    for (int seg = 0; seg < 8; seg++) {
        sum  += g_psum[((z * BB + b)  * 8 + seg) * CC + c];
        sq   += g_psq [((z * BB + b)  * 8 + seg) * CC + c];
        sums += g_psum[((z * BB + sb) * 8 + seg) * CC + c];
        sqs  += g_psq [((z * BB + sb) * 8 + seg) * CC + c];
    }
    float mean  = sum  * (1.0f / SS);
    float means = sums * (1.0f / SS);
    float sd  = sqrtf((sq  - sum  * mean ) * (1.0f / (SS - 1)) + EPSV);
    float sds = sqrtf((sqs - sums * means) * (1.0f / (SS - 1)) + EPSV);
    float scl = sds / sd;
    g_scl[i] = scl;
    g_shf[i] = means - mean * scl;
}

// ---------------------------------------------------------------------------
// apply AdaIN to K only (Q's affine is fused into attention Q staging)
// ---------------------------------------------------------------------------
__global__ void k_apply()
{
    const int TOT4  = BB * SS * CC / 4;
    const int per_t = SS * CC / 4;
    int i4 = blockIdx.x * 256 + threadIdx.x;
    if (i4 >= TOT4) return;
    int b = i4 / per_t;
    int r = i4 % per_t;
    int c = (r % (CC / 4)) * 4;
    uint2 xin = ((const uint2*)(g_kp + (size_t)b * SS * CC))[r];
    __half2 h0 = *(__half2*)&xin.x;
    __half2 h1 = *(__half2*)&xin.y;
    float4 scl = *(const float4*)&g_scl[(BB + b) * CC + c];
    float4 shf = *(const float4*)&g_shf[(BB + b) * CC + c];
    uint2 t;
    t.x = pack_h2(fmaf(__low2float(h0),  scl.x, shf.x),
                  fmaf(__high2float(h0), scl.y, shf.y));
    t.y = pack_h2(fmaf(__low2float(h1),  scl.z, shf.z),
                  fmaf(__high2float(h1), scl.w, shf.w));
    ((uint2*)(g_kh + (size_t)b * SS * CC))[r] = t;
}

// ---------------------------------------------------------------------------
// Flash attention, fp16 m16n8k16 mma, persistent CTAs + atomic work queue.
// Q AdaIN affine fused into the Q staging pass. V transposed on the fly by
// ldmatrix.x4.trans. 3-stage cp.async ring, one barrier per chunk, P straight
// from the S accumulator, style dedup, max-free softmax (exp2; bias = +1.0).
// ---------------------------------------------------------------------------
#define KS_OFF(s) ((s) * 18432)
#define VS_OFF(s) ((s) * 18432 + 9216)
#define ATT_SMEM  (3 * 18432)    // 55296 bytes
#define N_ITEMS 640

__global__ __launch_bounds__(256, 2) void k_attn_mma()
{
    extern __shared__ __align__(16) uint32_t sm[];
    __shared__ int s_item;
    char* smc = (char*)sm;

    const int tid  = threadIdx.x;
    const int warp = tid >> 5, lane = tid & 31;
    const int tg   = lane & 3, gid = lane >> 2;
    const int wq   = warp * 16;

    const uint32_t smb = smem_u32(sm);
    const int frow = tid >> 3, fcol = tid & 7;

    const int lr = lane & 7;
    const uint32_t aoff = ((wq + ((lane >> 3) & 1) * 8 + lr) * 72
                           + ((lane >> 4) & 1) * 8) * 2;
    const uint32_t kvoff = (((lane >> 4) * 8 + lr) * 72
                           + ((lane >> 3) & 1) * 8) * 2;
    const uint32_t vtoff = (uint32_t)((((lane >> 3) & 1) * 8 + lr) * 144
                           + (lane >> 4) * 16);

    while (true) {
        if (tid == 0) s_item = atomicAdd(&g_ctr, 1);
        __syncthreads();
        const int item = s_item;
        if (item >= N_ITEMS) break;

        // decode: items 0..319 long (b=1,3), 320..639 short (b=0,2)
        int b, rem;
        if (item < 320) { b = 1 + 2 * (item / 160); rem = item % 160; }
        else            { int j = item - 320; b = 2 * (j / 160); rem = j % 160; }
        const int h  = rem / 8;
        const int q0 = (rem % 8) * 128;
        const int sbv = (b < BB / 2) ? 0 : BB / 2;
        const int nch = (b == sbv) ? 16 : 32;

        // ---- stage Q tile (128x64) with fused AdaIN affine ----
        {
            const __half* Qg = g_qp + (size_t)(b * SS + q0) * CC + h * DD;
            const float* sclQ = g_scl + b * CC + h * DD;   // z = 0
            const float* shfQ = g_shf + b * CC + h * DD;
#pragma unroll
            for (int i = 0; i < 4; i++) {
                int fid = tid + i * 256;
                int row = fid >> 3, c8 = fid & 7;
                uint4 raw = *(const uint4*)(Qg + (size_t)row * CC + c8 * 8);
                float4 s0 = *(const float4*)(sclQ + c8 * 8);
                float4 s1 = *(const float4*)(sclQ + c8 * 8 + 4);
                float4 f0 = *(const float4*)(shfQ + c8 * 8);
                float4 f1 = *(const float4*)(shfQ + c8 * 8 + 4);
                __half2 x0 = *(__half2*)&raw.x;
                __half2 x1 = *(__half2*)&raw.y;
                __half2 x2 = *(__half2*)&raw.z;
                __half2 x3 = *(__half2*)&raw.w;
                uint4 outv;
                outv.x = pack_h2(fmaf(__low2float(x0),  s0.x, f0.x),
                                 fmaf(__high2float(x0), s0.y, f0.y));
                outv.y = pack_h2(fmaf(__low2float(x1),  s0.z, f0.z),
                                 fmaf(__high2float(x1), s0.w, f0.w));
                outv.z = pack_h2(fmaf(__low2float(x2),  s1.x, f1.x),
                                 fmaf(__high2float(x2), s1.y, f1.y));
                outv.w = pack_h2(fmaf(__low2float(x3),  s1.z, f1.z),
                                 fmaf(__high2float(x3), s1.w, f1.w));
                *(uint4*)(smc + row * 144 + c8 * 16) = outv;
            }
        }
        __syncthreads();

        uint32_t qf[4][4];
#pragma unroll
        for (int ks = 0; ks < 4; ks++) LDSM_X4(qf[ks], smb + aoff + ks * 32);
        __syncthreads();   // Q reads done; stage 0 free for chunk 0

        float o[8][4];
#pragma unroll
        for (int n_ = 0; n_ < 8; n_++)
#pragma unroll
            for (int r = 0; r < 4; r++) o[n_][r] = 0.f;
        float l0r = 0.f, l1r = 0.f;

        const __half* Kbase0 = g_kh + (size_t)b * SS * CC + h * DD;
        const __half* Kbase1 = g_kh + (size_t)sbv * SS * CC + h * DD;
        const __half* Vbase0 = g_vh + (size_t)b * SS * CC + h * DD;
        const __half* Vbase1 = g_vh + (size_t)sbv * SS * CC + h * DD;

#define AISSUE(c, s) do { \
    const int _self = ((c) < 16); \
    const int _kr   = (_self ? (c) : (c) - 16) * 64; \
    const __half* _Kg = (_self ? Kbase0 : Kbase1) + (size_t)_kr * CC; \
    const __half* _Vg = (_self ? Vbase0 : Vbase1) + (size_t)_kr * CC; \
    uint32_t _kd = smb + KS_OFF(s) + frow * 144 + fcol * 16; \
    uint32_t _vd = smb + VS_OFF(s) + frow * 144 + fcol * 16; \
    _Pragma("unroll") \
    for (int _i = 0; _i < 2; _i++) { \
        int _row = frow + _i * 32; \
        CP_ASYNC16(_kd + _i * 32 * 144, _Kg + (size_t)_row * CC + fcol * 8); \
        CP_ASYNC16(_vd + _i * 32 * 144, _Vg + (size_t)_row * CC + fcol * 8); \
    } \
} while (0)

        AISSUE(0, 0); CP_COMMIT();
        AISSUE(1, 1); CP_COMMIT();

        int st = 0;
        for (int ch = 0; ch < nch; ch++) {
            const float b2 = (ch < 16) ? 0.f : 1.0f;   // log2(e)*ln2 == 1

            CP_WAIT1();
            __syncthreads();

            int is_ = st + 2; if (is_ >= 3) is_ -= 3;
            if (ch + 2 < nch) AISSUE(ch + 2, is_);
            CP_COMMIT();

            const uint32_t kbase = smb + KS_OFF(st) + kvoff;
            const uint32_t vbase = smb + VS_OFF(st) + vtoff;

            // ---- S = Q @ K^T (16 x 64 per warp), 4 k16 steps ----
            float sacc[8][4];
#pragma unroll
            for (int n_ = 0; n_ < 8; n_++)
#pragma unroll
                for (int r = 0; r < 4; r++) sacc[n_][r] = 0.f;

#pragma unroll
            for (int ks = 0; ks < 4; ks++) {
                uint32_t bf[4][4];
#pragma unroll
                for (int np = 0; np < 4; np++)
                    LDSM_X4(bf[np], kbase + np * 16 * 144 + ks * 32);
#pragma unroll
                for (int np = 0; np < 4; np++) {
                    mma_16816(sacc[2*np],     qf[ks], bf[np][0], bf[np][1]);
                    mma_16816(sacc[2*np + 1], qf[ks], bf[np][2], bf[np][3]);
                }
            }

            // ---- fused softmax + PV (V fragments via trans-LDSM) ----
#pragma unroll
            for (int j = 0; j < 4; j++) {
                float e0 = fexp2(fmaf(sacc[2*j][0], SC2, b2));
                float e1 = fexp2(fmaf(sacc[2*j][1], SC2, b2));
                float e2 = fexp2(fmaf(sacc[2*j][2], SC2, b2));
                float e3 = fexp2(fmaf(sacc[2*j][3], SC2, b2));
                float f0 = fexp2(fmaf(sacc[2*j+1][0], SC2, b2));
                float f1 = fexp2(fmaf(sacc[2*j+1][1], SC2, b2));
                float f2 = fexp2(fmaf(sacc[2*j+1][2], SC2, b2));
                float f3 = fexp2(fmaf(sacc[2*j+1][3], SC2, b2));
                l0r += (e0 + e1) + (f0 + f1);
                l1r += (e2 + e3) + (f2 + f3);
                uint32_t pf[4];
                pf[0] = pack_h2(e0, e1);
                pf[1] = pack_h2(e2, e3);
                pf[2] = pack_h2(f0, f1);
                pf[3] = pack_h2(f2, f3);

                uint32_t bf[4][4];
#pragma unroll
                for (int np = 0; np < 4; np++)
                    LDSM_X4T(bf[np], vbase + j * 16 * 144 + np * 32);
#pragma unroll
                for (int np = 0; np < 4; np++) {
                    mma_16816(o[2*np],     pf, bf[np][0], bf[np][1]);
                    mma_16816(o[2*np + 1], pf, bf[np][2], bf[np][3]);
                }
            }

            if (++st == 3) st = 0;
        }

        // ---- epilogue: quad-reduce row sums, normalize, store fp16 ----
        l0r += __shfl_xor_sync(0xffffffffu, l0r, 1);
        l0r += __shfl_xor_sync(0xffffffffu, l0r, 2);
        l1r += __shfl_xor_sync(0xffffffffu, l1r, 1);
        l1r += __shfl_xor_sync(0xffffffffu, l1r, 2);
        const float inv0 = 1.0f / l0r, inv1 = 1.0f / l1r;
        __half* Og = g_attnh + (size_t)(b * SS + q0 + wq) * CC + h * DD;
#pragma unroll
        for (int n_ = 0; n_ < 8; n_++) {
            int col = n_ * 8 + tg * 2;
            uint32_t lo = pack_h2(o[n_][0] * inv0, o[n_][1] * inv0);
            uint32_t hi = pack_h2(o[n_][2] * inv1, o[n_][3] * inv1);
            *(uint32_t*)(Og + (size_t)gid * CC + col)       = lo;
            *(uint32_t*)(Og + (size_t)(gid + 8) * CC + col) = hi;
        }
    }
}

// ---------------------------------------------------------------------------
extern "C" void kernel_launch(void* const* d_in, const int* in_sizes, int n_in,
                              void* d_out, int out_size)
{
    (void)in_sizes; (void)n_in; (void)out_size;
    const float* X  = (const float*)d_in[0];
    const float* Wq = (const float*)d_in[1];
    const float* Wk = (const float*)d_in[2];
    const float* Wv = (const float*)d_in[3];
    const float* Wo = (const float*)d_in[4];
    const float* bo = (const float*)d_in[5];
    float* out = (float*)d_out;

    cudaFuncSetAttribute(k_attn_mma, cudaFuncAttributeMaxDynamicSharedMemorySize,
                         ATT_SMEM);
    cudaFuncSetAttribute(k_qkv_mma, cudaFuncAttributeMaxDynamicSharedMemorySize,
                         GEMM_SMEM);
    cudaFuncSetAttribute(k_proj_mma, cudaFuncAttributeMaxDynamicSharedMemorySize,
                         GEMM_SMEM);

    k_cvt<<<(CVT_F4 + 255) / 256, 256>>>(X, Wq, Wk, Wv, Wo);
    k_qkv_mma<<<dim3(CC / 128, (BB * SS) / 128, 3), 256, GEMM_SMEM>>>();
    k_finalize<<<(2 * BB * CC + 255) / 256, 256>>>();
    k_apply<<<(BB * SS * CC / 4 + 255) / 256, 256>>>();
    k_attn_mma<<<304, 256, ATT_SMEM>>>();
    k_proj_mma<<<dim3(CC / 128, (BB * SS) / 128), 256, GEMM_SMEM>>>(bo, out);
}

// round 17
// speedup vs baseline: 1.4974x; 1.4974x over previous
#include <cuda_runtime.h>
#include <cuda_fp16.h>
#include <cstdint>
#include <math.h>

// Problem constants
#define BB 4
#define SS 1024
#define CC 1280
#define HH 20
#define DD 64
#define SC2 0.18033688011112042f      // 64^-0.5 * log2(e)
#define EPSV 1e-5f

// ---------------- scratch (static device allocations are allowed) -----------
#define XN (BB*SS*CC)     // 5242880
#define WN (CC*CC)        // 1638400
__device__ __align__(16) __half g_xh[XN + 4*WN];   // fp16 [X | Wq | Wk | Wv | Wo]
__device__ __align__(16) __half g_qp[BB*SS*CC];    // fp16 Q (pre-AdaIN)
__device__ __align__(16) __half g_kp[BB*SS*CC];    // fp16 K (pre-AdaIN)
__device__ __align__(16) __half g_qh[BB*SS*CC];    // fp16 AdaIN'd Q
__device__ __align__(16) __half g_kh[BB*SS*CC];    // fp16 AdaIN'd K
__device__ __align__(16) __half g_vh[BB*SS*CC];    // fp16 V (from GEMM)
__device__ __align__(16) __half g_attnh[BB*SS*CC]; // fp16 attention output
__device__ float  g_psum[2*BB*16*CC];
__device__ float  g_psq [2*BB*16*CC];
__device__ float  g_scl[2*BB*CC];
__device__ float  g_shf[2*BB*CC];
__device__ int    g_ctr;                           // attention work-queue counter

// =================== helpers (sm_75+/sm_80+ PTX, base-target safe) =========
__device__ __forceinline__ float fexp2(float x) {
    float y;
    asm("ex2.approx.f32 %0, %1;" : "=f"(y) : "f"(x));
    return y;
}

__device__ __forceinline__ void mma_16816(
    float c[4], const uint32_t a[4], uint32_t b0, uint32_t b1)
{
    asm volatile(
        "mma.sync.aligned.m16n8k16.row.col.f32.f16.f16.f32 "
        "{%0,%1,%2,%3}, {%4,%5,%6,%7}, {%8,%9}, {%0,%1,%2,%3};\n"
        : "+f"(c[0]), "+f"(c[1]), "+f"(c[2]), "+f"(c[3])
        : "r"(a[0]), "r"(a[1]), "r"(a[2]), "r"(a[3]), "r"(b0), "r"(b1));
}

__device__ __forceinline__ uint32_t smem_u32(const void* p) {
    uint32_t a;
    asm("{ .reg .u64 t; cvta.to.shared.u64 t, %1; cvt.u32.u64 %0, t; }"
        : "=r"(a) : "l"(p));
    return a;
}

__device__ __forceinline__ uint32_t pack_h2(float a, float b) {
    __half2 t = __floats2half2_rn(a, b);
    return *(uint32_t*)&t;
}

#define LDSM_X4(R, addr) \
    asm volatile("ldmatrix.sync.aligned.m8n8.x4.shared.b16 {%0,%1,%2,%3}, [%4];" \
        : "=r"((R)[0]), "=r"((R)[1]), "=r"((R)[2]), "=r"((R)[3]) : "r"(addr))

#define LDSM_X4T(R, addr) \
    asm volatile("ldmatrix.sync.aligned.m8n8.x4.trans.shared.b16 {%0,%1,%2,%3}, [%4];" \
        : "=r"((R)[0]), "=r"((R)[1]), "=r"((R)[2]), "=r"((R)[3]) : "r"(addr))

#define CP_ASYNC16(dst, src) \
    asm volatile("cp.async.cg.shared.global [%0], [%1], 16;" \
        :: "r"(dst), "l"(src))
#define CP_COMMIT() asm volatile("cp.async.commit_group;")
#define CP_WAIT1()  asm volatile("cp.async.wait_group 1;")

// ---------------------------------------------------------------------------
// fp16 conversion pass over [X | Wq | Wk | Wv | Wo] + work-queue reset
// ---------------------------------------------------------------------------
#define CVT_F4 ((XN + 4*WN) / 4)
__global__ __launch_bounds__(256) void k_cvt(
    const float* __restrict__ X,  const float* __restrict__ Wq,
    const float* __restrict__ Wk, const float* __restrict__ Wv,
    const float* __restrict__ Wo)
{
    if (blockIdx.x == 0 && threadIdx.x == 0) g_ctr = 0;
    int i4 = blockIdx.x * 256 + threadIdx.x;
    if (i4 >= CVT_F4) return;
    const float* src;
    int base;
    if      (i4 < XN/4)          { src = X;  base = 0; }
    else if (i4 < (XN+WN)/4)     { src = Wq; base = XN/4; }
    else if (i4 < (XN+2*WN)/4)   { src = Wk; base = (XN+WN)/4; }
    else if (i4 < (XN+3*WN)/4)   { src = Wv; base = (XN+2*WN)/4; }
    else                         { src = Wo; base = (XN+3*WN)/4; }
    float4 v = ((const float4*)src)[i4 - base];
    uint2 t;
    t.x = pack_h2(v.x, v.y);
    t.y = pack_h2(v.z, v.w);
    ((uint2*)g_xh)[i4] = t;
}

// ---------------------------------------------------------------------------
// Tensor-core fp16 GEMM (fp32 accum): C = A @ W^T (+bias). Inputs fp16.
// Block 128x128, BK=32 fp16, 3-stage cp.async, one barrier per k-tile.
// Epilogue writes fp32 (CoutF) or fp16 (CoutH).
// ---------------------------------------------------------------------------
#define GKT (CC / 32)   // 40 k-tiles
#define GST 10240
#define GBOFF 30720
#define GEMM_SMEM 61440

#define GISSUE(t, s) do { \
    uint32_t _da = base + (s) * GST + stoff; \
    uint32_t _db = base + GBOFF + (s) * GST + stoff; \
    const __half* _An = Ap + (t) * 32; \
    const __half* _Bn = Bp + (t) * 32; \
    CP_ASYNC16(_da,      _An); \
    CP_ASYNC16(_da + 16, _An + 8); \
    CP_ASYNC16(_db,      _Bn); \
    CP_ASYNC16(_db + 16, _Bn + 8); \
} while (0)

__device__ __forceinline__ void gemm_mma_body(
    const __half* __restrict__ A, const __half* __restrict__ W,
    const float* __restrict__ bias, float* __restrict__ CoutF,
    __half* __restrict__ CoutH)
{
    extern __shared__ __align__(16) uint32_t gsm[];

    const int tid  = threadIdx.x;
    const int warp = tid >> 5, lane = tid & 31;
    const int wm   = (warp & 3) * 32;
    const int wn   = (warp >> 2) * 64;
    const int tg   = lane & 3, gid = lane >> 2;
    const int m0   = blockIdx.y * 128;
    const int n0   = blockIdx.x * 128;

    const int lrow = tid >> 1;
    const int lc   = (tid & 1) * 16;
    const __half* Ap = A + (size_t)(m0 + lrow) * CC + lc;
    const __half* Bp = W + (size_t)(n0 + lrow) * CC + lc;

    const uint32_t base  = smem_u32(gsm);
    const uint32_t stoff = (uint32_t)(lrow * 40 + lc) * 2;

    const int lr = lane & 7;
    const uint32_t aoff = ((wm + ((lane >> 3) & 1) * 8 + lr) * 40
                           + ((lane >> 4) & 1) * 8) * 2;
    const uint32_t boff = ((wn + (lane >> 4) * 8 + lr) * 40
                           + ((lane >> 3) & 1) * 8) * 2;

    float acc[2][8][4];
#pragma unroll
    for (int im = 0; im < 2; im++)
#pragma unroll
        for (int in_ = 0; in_ < 8; in_++)
#pragma unroll
            for (int r = 0; r < 4; r++) acc[im][in_][r] = 0.f;

    GISSUE(0, 0); CP_COMMIT();
    GISSUE(1, 1); CP_COMMIT();

    int cs = 0;
    for (int kt = 0; kt < GKT; kt++) {
        CP_WAIT1();
        __syncthreads();

        int is_ = cs + 2; if (is_ >= 3) is_ -= 3;
        if (kt + 2 < GKT) GISSUE(kt + 2, is_);
        CP_COMMIT();

        const uint32_t sal = base + cs * GST + aoff;
        const uint32_t sbl = base + GBOFF + cs * GST + boff;
#pragma unroll
        for (int ks = 0; ks < 2; ks++) {
            uint32_t af[2][4];
            uint32_t bf[4][4];
            LDSM_X4(af[0], sal + ks * 32);
            LDSM_X4(af[1], sal + 16 * 80 + ks * 32);
#pragma unroll
            for (int np = 0; np < 4; np++)
                LDSM_X4(bf[np], sbl + np * 16 * 80 + ks * 32);
#pragma unroll
            for (int np = 0; np < 4; np++) {
                mma_16816(acc[0][2*np],     af[0], bf[np][0], bf[np][1]);
                mma_16816(acc[0][2*np + 1], af[0], bf[np][2], bf[np][3]);
                mma_16816(acc[1][2*np],     af[1], bf[np][0], bf[np][1]);
                mma_16816(acc[1][2*np + 1], af[1], bf[np][2], bf[np][3]);
            }
        }
        if (++cs == 3) cs = 0;
    }

#pragma unroll
    for (int im = 0; im < 2; im++) {
        int row = m0 + wm + im * 16 + gid;
#pragma unroll
        for (int in_ = 0; in_ < 8; in_++) {
            int col = n0 + wn + in_ * 8 + tg * 2;
            if (CoutH) {
                uint32_t lo = pack_h2(acc[im][in_][0], acc[im][in_][1]);
                uint32_t hi = pack_h2(acc[im][in_][2], acc[im][in_][3]);
                *(uint32_t*)(CoutH + (size_t)row * CC + col)       = lo;
                *(uint32_t*)(CoutH + (size_t)(row + 8) * CC + col) = hi;
            } else {
                float b0v = 0.f, b1v = 0.f;
                if (bias) { b0v = bias[col]; b1v = bias[col + 1]; }
                float2 lo = make_float2(acc[im][in_][0] + b0v, acc[im][in_][1] + b1v);
                float2 hi = make_float2(acc[im][in_][2] + b0v, acc[im][in_][3] + b1v);
                *(float2*)(CoutF + (size_t)row * CC + col)       = lo;
                *(float2*)(CoutF + (size_t)(row + 8) * CC + col) = hi;
            }
        }
    }
}

__global__ __launch_bounds__(256) void k_qkv_mma()
{
    const __half* X = g_xh;
    const __half* W = g_xh + XN + (size_t)blockIdx.z * WN;
    if (blockIdx.z == 0)      gemm_mma_body(X, W, nullptr, nullptr, g_qp);
    else if (blockIdx.z == 1) gemm_mma_body(X, W, nullptr, nullptr, g_kp);
    else                      gemm_mma_body(X, W, nullptr, nullptr, g_vh);
}

__global__ __launch_bounds__(256) void k_proj_mma(
    const float* __restrict__ bo, float* __restrict__ out)
{
    gemm_mma_body(g_attnh, g_xh + XN + 3 * (size_t)WN, bo, out, nullptr);
}

// ---------------------------------------------------------------------------
// AdaIN stats (split-S, 16 segments, fp16 inputs, fp32 accum)
// ---------------------------------------------------------------------------
__global__ void k_stats()
{
    const int c   = blockIdx.x * 128 + threadIdx.x;
    const int b   = blockIdx.y;
    const int z   = blockIdx.z >> 4;
    const int seg = blockIdx.z & 15;
    const __half* src = z ? g_kp : g_qp;
    const __half* p = src + ((size_t)b * SS + seg * 64) * CC + c;

    float s0 = 0, s1 = 0, q0 = 0, q1 = 0;
#pragma unroll 4
    for (int s = 0; s < 64; s += 2) {
        float x0 = __half2float(p[(size_t)(s + 0) * CC]);
        float x1 = __half2float(p[(size_t)(s + 1) * CC]);
        s0 += x0; q0 = fmaf(x0, x0, q0);
        s1 += x1; q1 = fmaf(x1, x1, q1);
    }
    int idx = ((z * BB + b) * 16 + seg) * CC + c;
    g_psum[idx] = s0 + s1;
    g_psq [idx] = q0 + q1;
}

__global__ void k_finalize()
{
    int i = blockIdx.x * 256 + threadIdx.x;
    if (i >= 2 * BB * CC) return;
    int c  = i % CC;
    int b  = (i / CC) % BB;
    int z  = i / (CC * BB);
    int sb = (b < BB / 2) ? 0 : BB / 2;

    float sum = 0, sq = 0, sums = 0, sqs = 0;
#pragma unroll
    for (int seg = 0; seg < 16; seg++) {
        sum  += g_psum[((z * BB + b)  * 16 + seg) * CC + c];
        sq   += g_psq [((z * BB + b)  * 16 + seg) * CC + c];
        sums += g_psum[((z * BB + sb) * 16 + seg) * CC + c];
        sqs  += g_psq [((z * BB + sb) * 16 + seg) * CC + c];
    }
    float mean  = sum  * (1.0f / SS);
    float means = sums * (1.0f / SS);
    float sd  = sqrtf((sq  - sum  * mean ) * (1.0f / (SS - 1)) + EPSV);
    float sds = sqrtf((sqs - sums * means) * (1.0f / (SS - 1)) + EPSV);
    float scl = sds / sd;
    g_scl[i] = scl;
    g_shf[i] = means - mean * scl;
}

__global__ void k_apply()
{
    const int TOT4  = 2 * BB * SS * CC / 4;
    const int per_t = SS * CC / 4;
    int i4 = blockIdx.x * 256 + threadIdx.x;
    if (i4 >= TOT4) return;
    int zb = i4 / per_t;
    int r  = i4 % per_t;
    int c  = (r % (CC / 4)) * 4;
    const __half* pb = (zb < BB) ? g_qp : g_kp;
    __half*       hb = (zb < BB) ? g_qh : g_kh;
    int b = zb & 3;
    uint2 xin = ((const uint2*)(pb + (size_t)b * SS * CC))[r];
    __half2 h0 = *(__half2*)&xin.x;
    __half2 h1 = *(__half2*)&xin.y;
    float4 scl = *(const float4*)&g_scl[zb * CC + c];
    float4 shf = *(const float4*)&g_shf[zb * CC + c];
    uint2 t;
    t.x = pack_h2(fmaf(__low2float(h0),  scl.x, shf.x),
                  fmaf(__high2float(h0), scl.y, shf.y));
    t.y = pack_h2(fmaf(__low2float(h1),  scl.z, shf.z),
                  fmaf(__high2float(h1), scl.w, shf.w));
    ((uint2*)(hb + (size_t)b * SS * CC))[r] = t;
}

// ---------------------------------------------------------------------------
// Flash attention, fp16 m16n8k16 mma, persistent CTAs + atomic work queue.
// V is loaded ROW-MAJOR (like K) and transposed on the fly by
// ldmatrix.x4.trans -> no separate V-transpose pass or buffer.
// 3-stage cp.async ring, one barrier per chunk, P straight from the S
// accumulator, style dedup, max-free softmax (exp2; style bias = +1.0).
// ---------------------------------------------------------------------------
#define KS_OFF(s) ((s) * 18432)
#define VS_OFF(s) ((s) * 18432 + 9216)
#define ATT_SMEM  (3 * 18432)    // 55296 bytes
#define N_ITEMS 640

__global__ __launch_bounds__(256, 2) void k_attn_mma()
{
    extern __shared__ __align__(16) uint32_t sm[];
    __shared__ int s_item;
    char* smc = (char*)sm;

    const int tid  = threadIdx.x;
    const int warp = tid >> 5, lane = tid & 31;
    const int tg   = lane & 3, gid = lane >> 2;
    const int wq   = warp * 16;

    const uint32_t smb = smem_u32(sm);
    const int frow = tid >> 3, fcol = tid & 7;

    const int lr = lane & 7;
    const uint32_t aoff = ((wq + ((lane >> 3) & 1) * 8 + lr) * 72
                           + ((lane >> 4) & 1) * 8) * 2;
    const uint32_t kvoff = (((lane >> 4) * 8 + lr) * 72
                           + ((lane >> 3) & 1) * 8) * 2;
    // trans-LDSM lane offsets for V (rows = keys, cols = d)
    const uint32_t vtoff = (uint32_t)((((lane >> 3) & 1) * 8 + lr) * 144
                           + (lane >> 4) * 16);

    while (true) {
        if (tid == 0) s_item = atomicAdd(&g_ctr, 1);
        __syncthreads();
        const int item = s_item;
        if (item >= N_ITEMS) break;

        // decode: items 0..319 long (b=1,3), 320..639 short (b=0,2)
        int b, rem;
        if (item < 320) { b = 1 + 2 * (item / 160); rem = item % 160; }
        else            { int j = item - 320; b = 2 * (j / 160); rem = j % 160; }
        const int h  = rem / 8;
        const int q0 = (rem % 8) * 128;
        const int sbv = (b < BB / 2) ? 0 : BB / 2;
        const int nch = (b == sbv) ? 16 : 32;

        // ---- stage Q tile (128x64 fp16) through stage-0, grab frags ----
        {
            const __half* Qg = g_qh + (size_t)(b * SS + q0) * CC + h * DD;
#pragma unroll
            for (int i = 0; i < 4; i++) {
                int fid = tid + i * 256;
                int row = fid >> 3, c8 = fid & 7;
                *(uint4*)(smc + row * 144 + c8 * 16) =
                    *(const uint4*)(Qg + (size_t)row * CC + c8 * 8);
            }
        }
        __syncthreads();

        uint32_t qf[4][4];
#pragma unroll
        for (int ks = 0; ks < 4; ks++) LDSM_X4(qf[ks], smb + aoff + ks * 32);
        __syncthreads();   // Q reads done; stage 0 free for chunk 0

        float o[8][4];
#pragma unroll
        for (int n_ = 0; n_ < 8; n_++)
#pragma unroll
            for (int r = 0; r < 4; r++) o[n_][r] = 0.f;
        float l0r = 0.f, l1r = 0.f;

        const __half* Kbase0 = g_kh + (size_t)b * SS * CC + h * DD;
        const __half* Kbase1 = g_kh + (size_t)sbv * SS * CC + h * DD;
        const __half* Vbase0 = g_vh + (size_t)b * SS * CC + h * DD;
        const __half* Vbase1 = g_vh + (size_t)sbv * SS * CC + h * DD;

#define AISSUE(c, s) do { \
    const int _self = ((c) < 16); \
    const int _kr   = (_self ? (c) : (c) - 16) * 64; \
    const __half* _Kg = (_self ? Kbase0 : Kbase1) + (size_t)_kr * CC; \
    const __half* _Vg = (_self ? Vbase0 : Vbase1) + (size_t)_kr * CC; \
    uint32_t _kd = smb + KS_OFF(s) + frow * 144 + fcol * 16; \
    uint32_t _vd = smb + VS_OFF(s) + frow * 144 + fcol * 16; \
    _Pragma("unroll") \
    for (int _i = 0; _i < 2; _i++) { \
        int _row = frow + _i * 32; \
        CP_ASYNC16(_kd + _i * 32 * 144, _Kg + (size_t)_row * CC + fcol * 8); \
        CP_ASYNC16(_vd + _i * 32 * 144, _Vg + (size_t)_row * CC + fcol * 8); \
    } \
} while (0)

        AISSUE(0, 0); CP_COMMIT();
        AISSUE(1, 1); CP_COMMIT();

        int st = 0;
        for (int ch = 0; ch < nch; ch++) {
            const float b2 = (ch < 16) ? 0.f : 1.0f;   // log2(e)*ln2 == 1

            CP_WAIT1();
            __syncthreads();

            int is_ = st + 2; if (is_ >= 3) is_ -= 3;
            if (ch + 2 < nch) AISSUE(ch + 2, is_);
            CP_COMMIT();

            const uint32_t kbase = smb + KS_OFF(st) + kvoff;
            const uint32_t vbase = smb + VS_OFF(st) + vtoff;

            // ---- S = Q @ K^T (16 x 64 per warp), 4 k16 steps ----
            float sacc[8][4];
#pragma unroll
            for (int n_ = 0; n_ < 8; n_++)
#pragma unroll
                for (int r = 0; r < 4; r++) sacc[n_][r] = 0.f;

#pragma unroll
            for (int ks = 0; ks < 4; ks++) {
                uint32_t bf[4][4];
#pragma unroll
                for (int np = 0; np < 4; np++)
                    LDSM_X4(bf[np], kbase + np * 16 * 144 + ks * 32);
#pragma unroll
                for (int np = 0; np < 4; np++) {
                    mma_16816(sacc[2*np],     qf[ks], bf[np][0], bf[np][1]);
                    mma_16816(sacc[2*np + 1], qf[ks], bf[np][2], bf[np][3]);
                }
            }

            // ---- fused softmax + PV (V fragments via trans-LDSM) ----
#pragma unroll
            for (int j = 0; j < 4; j++) {
                float e0 = fexp2(fmaf(sacc[2*j][0], SC2, b2));
                float e1 = fexp2(fmaf(sacc[2*j][1], SC2, b2));
                float e2 = fexp2(fmaf(sacc[2*j][2], SC2, b2));
                float e3 = fexp2(fmaf(sacc[2*j][3], SC2, b2));
                float f0 = fexp2(fmaf(sacc[2*j+1][0], SC2, b2));
                float f1 = fexp2(fmaf(sacc[2*j+1][1], SC2, b2));
                float f2 = fexp2(fmaf(sacc[2*j+1][2], SC2, b2));
                float f3 = fexp2(fmaf(sacc[2*j+1][3], SC2, b2));
                l0r += (e0 + e1) + (f0 + f1);
                l1r += (e2 + e3) + (f2 + f3);
                uint32_t pf[4];
                pf[0] = pack_h2(e0, e1);
                pf[1] = pack_h2(e2, e3);
                pf[2] = pack_h2(f0, f1);
                pf[3] = pack_h2(f2, f3);

                uint32_t bf[4][4];
#pragma unroll
                for (int np = 0; np < 4; np++)
                    LDSM_X4T(bf[np], vbase + j * 16 * 144 + np * 32);
#pragma unroll
                for (int np = 0; np < 4; np++) {
                    mma_16816(o[2*np],     pf, bf[np][0], bf[np][1]);
                    mma_16816(o[2*np + 1], pf, bf[np][2], bf[np][3]);
                }
            }

            if (++st == 3) st = 0;
        }

        // ---- epilogue: quad-reduce row sums, normalize, store fp16 ----
        l0r += __shfl_xor_sync(0xffffffffu, l0r, 1);
        l0r += __shfl_xor_sync(0xffffffffu, l0r, 2);
        l1r += __shfl_xor_sync(0xffffffffu, l1r, 1);
        l1r += __shfl_xor_sync(0xffffffffu, l1r, 2);
        const float inv0 = 1.0f / l0r, inv1 = 1.0f / l1r;
        __half* Og = g_attnh + (size_t)(b * SS + q0 + wq) * CC + h * DD;
#pragma unroll
        for (int n_ = 0; n_ < 8; n_++) {
            int col = n_ * 8 + tg * 2;
            uint32_t lo = pack_h2(o[n_][0] * inv0, o[n_][1] * inv0);
            uint32_t hi = pack_h2(o[n_][2] * inv1, o[n_][3] * inv1);
            *(uint32_t*)(Og + (size_t)gid * CC + col)       = lo;
            *(uint32_t*)(Og + (size_t)(gid + 8) * CC + col) = hi;
        }
    }
}

// ---------------------------------------------------------------------------
extern "C" void kernel_launch(void* const* d_in, const int* in_sizes, int n_in,
                              void* d_out, int out_size)
{
    (void)in_sizes; (void)n_in; (void)out_size;
    const float* X  = (const float*)d_in[0];
    const float* Wq = (const float*)d_in[1];
    const float* Wk = (const float*)d_in[2];
    const float* Wv = (const float*)d_in[3];
    const float* Wo = (const float*)d_in[4];
    const float* bo = (const float*)d_in[5];
    float* out = (float*)d_out;

    cudaFuncSetAttribute(k_attn_mma, cudaFuncAttributeMaxDynamicSharedMemorySize,
                         ATT_SMEM);
    cudaFuncSetAttribute(k_qkv_mma, cudaFuncAttributeMaxDynamicSharedMemorySize,
                         GEMM_SMEM);
    cudaFuncSetAttribute(k_proj_mma, cudaFuncAttributeMaxDynamicSharedMemorySize,
                         GEMM_SMEM);

    k_cvt<<<(CVT_F4 + 255) / 256, 256>>>(X, Wq, Wk, Wv, Wo);
    k_qkv_mma<<<dim3(CC / 128, (BB * SS) / 128, 3), 256, GEMM_SMEM>>>();
    k_stats<<<dim3(CC / 128, BB, 32), 128>>>();
    k_finalize<<<(2 * BB * CC + 255) / 256, 256>>>();
    k_apply<<<(2 * BB * SS * CC / 4 + 255) / 256, 256>>>();
    k_attn_mma<<<304, 256, ATT_SMEM>>>();
    k_proj_mma<<<dim3(CC / 128, (BB * SS) / 128), 256, GEMM_SMEM>>>(bo, out);
}